// round 4
// baseline (speedup 1.0000x reference)
#include <cuda_runtime.h>
#include <math.h>

#define NB 16
#define NM 64
#define NA 3
#define NC 80
#define CH 85

// layer cells: 16*3*80*80 = 307200, 76800, 19200 ; total 403200
#define L0_CELLS 307200
#define L1_CELLS 76800
#define L2_CELLS 19200
#define TOT_CELLS 403200
#define NBITWORDS 12600   // 403200/32

__device__ unsigned int g_bits[NBITWORDS];
// per layer 5 slots: [npos, cls_sum, bbox_sum, obj_corr, obj_sum]
__device__ double g_acc[16];

__global__ void zero_k() {
    int i = blockIdx.x * blockDim.x + threadIdx.x;
    if (i < NBITWORDS) g_bits[i] = 0u;
    if (i < 16) g_acc[i] = 0.0;
}

__device__ __forceinline__ float softplusf(float x) {
    return fmaxf(x, 0.f) + log1pf(expf(-fabsf(x)));
}

__global__ void match_k(const float* __restrict__ p3,
                        const float* __restrict__ p4,
                        const float* __restrict__ p5,
                        const float* __restrict__ boxes,
                        const int*   __restrict__ labels,
                        const unsigned char* __restrict__ valid,
                        const float* __restrict__ anchors) {
    int t = blockIdx.x * blockDim.x + threadIdx.x;
    if (t >= 3 * NB * NM) return;
    int l  = t / (NB * NM);
    int bm = t - l * (NB * NM);
    int b  = bm / NM;

    int gw = 80 >> l;
    int gh = 80 >> l;

    const float* bx = boxes + (size_t)bm * 4;
    float x1 = bx[0], y1 = bx[1], x2 = bx[2], y2 = bx[3];
    float cx = (x1 + x2) * 0.5f * (float)gw;
    float cy = (y1 + y2) * 0.5f * (float)gh;
    float w  = (x2 - x1) * (float)gw;
    float h  = (y2 - y1) * (float)gh;

    // best anchor by wh-IoU (first-max semantics via strict >)
    float best = -1.0f; int ba = 0;
#pragma unroll
    for (int a = 0; a < 3; a++) {
        float aw = anchors[l * 6 + a * 2 + 0];
        float ah = anchors[l * 6 + a * 2 + 1];
        float inter = fminf(w, aw) * fminf(h, ah);
        float uni   = w * h + aw * ah - inter;
        float iou   = inter / (uni + 1e-6f);
        if (iou > best) { best = iou; ba = a; }
    }
    bool pos = (valid[bm] != 0) && (best > 0.5f);
    if (!pos) return;

    int gx = min(max((int)cx, 0), gw - 1);
    int gy = min(max((int)cy, 0), gh - 1);

    const float* pred = (l == 0) ? p3 : ((l == 1) ? p4 : p5);
    long cell = (((long)(b * 3 + ba) * gh + gy) * gw + gx);
    const float* row = pred + cell * CH;

    // dedup bitset over all layers' cells (matches .at[].max scatter semantics)
    long gcell = cell + ((l == 0) ? 0 : ((l == 1) ? L0_CELLS : (L0_CELLS + L1_CELLS)));
    unsigned int mask = 1u << ((unsigned)gcell & 31u);
    unsigned int old  = atomicOr(&g_bits[gcell >> 5], mask);
    if (!(old & mask)) {
        // obj correction: BCE(x,1) - BCE(x,0) = -x for each unique positive cell
        atomicAdd(&g_acc[l * 5 + 3], -(double)row[4]);
    }

    atomicAdd(&g_acc[l * 5 + 0], 1.0);

    // classification BCE over 80 classes vs onehot(label)
    int lab = labels[bm];
    float cls = 0.f;
#pragma unroll 4
    for (int c = 0; c < NC; c++) {
        float xl = row[5 + c];
        float tt = (c == lab) ? 1.f : 0.f;
        cls += fmaxf(xl, 0.f) - xl * tt + log1pf(expf(-fabsf(xl)));
    }
    atomicAdd(&g_acc[l * 5 + 1], (double)cls);

    // CIoU-ish loss (matches reference exactly)
    float pcx = row[0], pcy = row[1], pw = row[2], ph = row[3];
    float px1 = pcx - pw * 0.5f, py1 = pcy - ph * 0.5f;
    float px2 = pcx + pw * 0.5f, py2 = pcy + ph * 0.5f;
    float tx1 = cx - w * 0.5f,  ty1 = cy - h * 0.5f;
    float tx2 = cx + w * 0.5f,  ty2 = cy + h * 0.5f;

    float ix1 = fmaxf(px1, tx1), iy1 = fmaxf(py1, ty1);
    float ix2 = fminf(px2, tx2), iy2 = fminf(py2, ty2);
    float inter = fmaxf(ix2 - ix1, 0.f) * fmaxf(iy2 - iy1, 0.f);
    float a1 = (px2 - px1) * (py2 - py1);
    float a2 = (tx2 - tx1) * (ty2 - ty1);
    float iou = inter / (a1 + a2 - inter + 1e-7f);
    float ccx = (px1 + px2) * 0.5f, ccy = (py1 + py2) * 0.5f;
    float dcx = (tx1 + tx2) * 0.5f, dcy = (ty1 + ty2) * 0.5f;
    float cd = (ccx - dcx) * (ccx - dcx) + (ccy - dcy) * (ccy - dcy);
    float ex1 = fminf(px1, tx1), ey1 = fminf(py1, ty1);
    float ex2 = fmaxf(px2, tx2), ey2 = fmaxf(py2, ty2);
    float dd = (ex2 - ex1) * (ex2 - ex1) + (ey2 - ey1) * (ey2 - ey1);
    float bbl = 1.f - (iou - cd / (dd + 1e-7f));
    atomicAdd(&g_acc[l * 5 + 2], (double)bbl);
}

// Strided objectness reduction: sum softplus(pred[...,4]) over every cell.
// Block partition: blocks [0,300) -> l0, [300,375) -> l1, [375,394) -> l2.
// Each block covers 256 threads * 4 cells = 1024 cells.
__global__ void obj_k(const float* __restrict__ p3,
                      const float* __restrict__ p4,
                      const float* __restrict__ p5) {
    int blk = blockIdx.x;
    int l, lblk, cells;
    const float* pred;
    if (blk < 300)      { l = 0; lblk = blk;       cells = L0_CELLS; pred = p3; }
    else if (blk < 375) { l = 1; lblk = blk - 300; cells = L1_CELLS; pred = p4; }
    else                { l = 2; lblk = blk - 375; cells = L2_CELLS; pred = p5; }

    int base = lblk * 1024 + threadIdx.x * 4;
    float x[4];
    int   ok[4];
#pragma unroll
    for (int k = 0; k < 4; k++) {
        int cell = base + k;
        ok[k] = (cell < cells);
        x[k] = ok[k] ? __ldg(pred + (size_t)cell * CH + 4) : 0.f;
    }
    float s = 0.f;
#pragma unroll
    for (int k = 0; k < 4; k++)
        if (ok[k]) s += softplusf(x[k]);

    __shared__ float sh[256];
    sh[threadIdx.x] = s;
    __syncthreads();
    for (int st = 128; st > 0; st >>= 1) {
        if (threadIdx.x < st) sh[threadIdx.x] += sh[threadIdx.x + st];
        __syncthreads();
    }
    if (threadIdx.x == 0)
        atomicAdd(&g_acc[l * 5 + 4], (double)sh[0]);
}

__global__ void final_k(float* __restrict__ out) {
    double total = 0.0;
    const double cellsd[3] = {(double)L0_CELLS, (double)L1_CELLS, (double)L2_CELLS};
    for (int l = 0; l < 3; l++) {
        double np = g_acc[l * 5 + 0];
        if (np > 0.0) {
            double denom = (np < 1.0) ? 1.0 : np;
            double cls = g_acc[l * 5 + 1] / (denom * (double)NC);
            double bb  = g_acc[l * 5 + 2] / denom;
            double obj = (g_acc[l * 5 + 4] + g_acc[l * 5 + 3]) / cellsd[l];
            total += 0.5 * cls + 1.0 * obj + 0.05 * bb;
        }
    }
    *out = (float)total;
}

extern "C" void kernel_launch(void* const* d_in, const int* in_sizes, int n_in,
                              void* d_out, int out_size) {
    const float* p3 = (const float*)d_in[0];
    const float* p4 = (const float*)d_in[1];
    const float* p5 = (const float*)d_in[2];
    const float* boxes = (const float*)d_in[3];
    const int*   labels = (const int*)d_in[4];
    const unsigned char* valid = (const unsigned char*)d_in[5];
    const float* anchors = (const float*)d_in[6];
    float* out = (float*)d_out;

    zero_k<<<50, 256>>>();
    match_k<<<24, 128>>>(p3, p4, p5, boxes, labels, valid, anchors);
    obj_k<<<394, 256>>>(p3, p4, p5);
    final_k<<<1, 1>>>(out);
}